// round 1
// baseline (speedup 1.0000x reference)
#include <cuda_runtime.h>

// FAVOR causal linear attention, chunked decomposition, fp32 SIMT.
// Shapes: B=1, H=8, D=64, DV=64, N=2048, M=128. Chunk C=128, 16 chunks/head.
// out[h,v,n] = (phi_q[n]·KVcum[n]) / (phi_q[n]·Kcum[n]),  phi = relu(X·F^T)
// (the 1/sqrt(M) scale cancels numerator/denominator exactly; omitted).

#define HH     8
#define DD     64
#define DVV    64
#define NSEQ   2048
#define MM     128
#define CHUNK  128
#define NCHUNK 16
#define DVA    65   // DV + ones column (normalizer state)
#define DVP    81   // padded V columns in kv kernel (odd stride, conflict-free)

// scratch (device globals: no allocation allowed in kernel_launch)
__device__ float g_phiQ[HH * MM * NSEQ];               // [h][m][n]
__device__ float g_phiK[HH * MM * NSEQ];               // [h][m][n]
__device__ float g_S [HH * NCHUNK * DVA * MM];         // [h][c][v][m]
__device__ float g_Sx[HH * NCHUNK * DVA * MM];         // exclusive prefix

// ---------------------------------------------------------------------------
// Kernel 1: phi = relu(X^T @ F^T), written transposed as [h][m][n].
// grid (NCHUNK, H, 2), block 256. smem = Xs[64][128] + Fs[128][65]
// ---------------------------------------------------------------------------
extern "C" __global__ void phi_kernel(const float* __restrict__ keys,
                                      const float* __restrict__ queries,
                                      const float* __restrict__ features) {
    extern __shared__ float sm[];
    float* Xs = sm;               // [DD][CHUNK]
    float* Fs = sm + DD * CHUNK;  // [MM][65] (padded)

    int c = blockIdx.x, h = blockIdx.y;
    const float* X  = blockIdx.z ? queries : keys;
    float*      outp = blockIdx.z ? g_phiQ : g_phiK;
    int n0 = c * CHUNK, tid = threadIdx.x;

    for (int idx = tid; idx < DD * CHUNK; idx += 256) {
        int d = idx >> 7, n = idx & 127;
        Xs[d * CHUNK + n] = X[(h * DD + d) * NSEQ + n0 + n];
    }
    for (int idx = tid; idx < MM * DD; idx += 256) {
        int m = idx >> 6, d = idx & 63;
        Fs[m * 65 + d] = features[idx];
    }
    __syncthreads();

    int tx = tid & 15, ty = tid >> 4;   // n = tx+16i (coalesced), m = ty+16j
    float acc[8][8];
    #pragma unroll
    for (int i = 0; i < 8; i++)
        #pragma unroll
        for (int j = 0; j < 8; j++) acc[i][j] = 0.f;

    #pragma unroll 4
    for (int d = 0; d < DD; d++) {
        float a[8], b[8];
        #pragma unroll
        for (int j = 0; j < 8; j++) a[j] = Fs[(ty + 16 * j) * 65 + d];
        #pragma unroll
        for (int i = 0; i < 8; i++) b[i] = Xs[d * CHUNK + tx + 16 * i];
        #pragma unroll
        for (int j = 0; j < 8; j++)
            #pragma unroll
            for (int i = 0; i < 8; i++) acc[i][j] = fmaf(a[j], b[i], acc[i][j]);
    }

    #pragma unroll
    for (int j = 0; j < 8; j++) {
        int m = ty + 16 * j;
        #pragma unroll
        for (int i = 0; i < 8; i++) {
            int n = tx + 16 * i;
            outp[(h * MM + m) * NSEQ + n0 + n] = fmaxf(acc[i][j], 0.f);
        }
    }
}

// ---------------------------------------------------------------------------
// Kernel 2: per-chunk state S_c[v][m] = sum_t phiK[m][t] * Vaug[t][v]
// (Vaug column 64 == 1.0 -> normalizer state). grid (NCHUNK,H), block 256.
// smem = Ks[128][129] + Vs[128][81]
// ---------------------------------------------------------------------------
extern "C" __global__ void kv_kernel(const float* __restrict__ values) {
    extern __shared__ float sm[];
    float* Ks = sm;              // [MM][129] padded
    float* Vs = sm + MM * 129;   // [CHUNK][DVP]

    int c = blockIdx.x, h = blockIdx.y, n0 = c * CHUNK, tid = threadIdx.x;

    for (int idx = tid; idx < MM * CHUNK; idx += 256) {
        int m = idx >> 7, t = idx & 127;
        Ks[m * 129 + t] = g_phiK[(h * MM + m) * NSEQ + n0 + t];
    }
    for (int idx = tid; idx < CHUNK * DVP; idx += 256)
        Vs[idx] = ((idx % DVP) == DVV) ? 1.0f : 0.0f;
    __syncthreads();  // ordering of init vs data fill below
    for (int idx = tid; idx < DVV * CHUNK; idx += 256) {
        int v = idx >> 7, t = idx & 127;
        Vs[t * DVP + v] = values[(h * DVV + v) * NSEQ + n0 + t];
    }
    __syncthreads();

    int tx = tid & 15, ty = tid >> 4;   // m = tx+16i, v = ty+16j (j<5)
    float acc[8][5];
    #pragma unroll
    for (int i = 0; i < 8; i++)
        #pragma unroll
        for (int j = 0; j < 5; j++) acc[i][j] = 0.f;

    #pragma unroll 2
    for (int t = 0; t < CHUNK; t++) {
        float a[8], b[5];
        #pragma unroll
        for (int i = 0; i < 8; i++) a[i] = Ks[(tx + 16 * i) * 129 + t];
        #pragma unroll
        for (int j = 0; j < 5; j++) b[j] = Vs[t * DVP + ty + 16 * j];
        #pragma unroll
        for (int j = 0; j < 5; j++)
            #pragma unroll
            for (int i = 0; i < 8; i++) acc[i][j] = fmaf(a[i], b[j], acc[i][j]);
    }

    long base = (long)(h * NCHUNK + c) * (DVA * MM);
    #pragma unroll
    for (int j = 0; j < 5; j++) {
        int v = ty + 16 * j;
        if (v < DVA) {
            #pragma unroll
            for (int i = 0; i < 8; i++)
                g_S[base + (long)v * MM + tx + 16 * i] = acc[i][j];
        }
    }
}

// ---------------------------------------------------------------------------
// Kernel 3: exclusive prefix over 16 chunks per head. grid H, block 256.
// ---------------------------------------------------------------------------
extern "C" __global__ void prefix_kernel() {
    int h = blockIdx.x, tid = threadIdx.x;
    const int E = DVA * MM;  // 8320
    float run[33];
    #pragma unroll
    for (int s = 0; s < 33; s++) run[s] = 0.f;
    for (int cc = 0; cc < NCHUNK; cc++) {
        long base = (long)(h * NCHUNK + cc) * E;
        #pragma unroll
        for (int s = 0; s < 33; s++) {
            int e = s * 256 + tid;
            if (e < E) {
                g_Sx[base + e] = run[s];
                run[s] += g_S[base + e];
            }
        }
    }
}

// ---------------------------------------------------------------------------
// Kernel 4: per-chunk output.
//   phase a: A[n][t] = phiQ[n]·phiK[t] (over m), causal mask t<=n
//   phase b: out[n][v] = sum_t A[n][t] V[t][v] + sum_m phiQ[n][m] S[m][v]
//            norm[n]   = sum_t A[n][t]         + sum_m phiQ[n][m] z[m]
// grid (NCHUNK,H), block 256. smem = Qs[128][128] + As[128][129] +
// (Ks[128][128] overlaid by Vs[128][65] + Ss[65][128]) = 198144 B
// ---------------------------------------------------------------------------
#define SM4_AS  (MM * CHUNK)            // 16384
#define SM4_KS  (SM4_AS + CHUNK * 129)  // 32896
#define SM4_FLOATS (SM4_KS + CHUNK * DVA + DVA * MM)  // 49536

extern "C" __global__ void out_kernel(const float* __restrict__ values,
                                      float* __restrict__ outp) {
    extern __shared__ float sm[];
    float* Qs = sm;            // [m][n], stride 128
    float* As = sm + SM4_AS;   // [t][n], stride 129
    float* Ks = sm + SM4_KS;   // phase a: [m][n]; phase b overlaid by Vs/Ss

    int c = blockIdx.x, h = blockIdx.y, n0 = c * CHUNK, tid = threadIdx.x;

    for (int idx = tid; idx < MM * CHUNK; idx += 256) {
        int m = idx >> 7, n = idx & 127;
        Qs[idx]            = g_phiQ[(h * MM + m) * NSEQ + n0 + n];
        Ks[m * CHUNK + n]  = g_phiK[(h * MM + m) * NSEQ + n0 + n];
    }
    __syncthreads();

    int tx = tid & 15, ty = tid >> 4;   // n = tx+16i, t = ty+16j
    float acc[8][8];
    #pragma unroll
    for (int i = 0; i < 8; i++)
        #pragma unroll
        for (int j = 0; j < 8; j++) acc[i][j] = 0.f;

    #pragma unroll 4
    for (int k = 0; k < MM; k++) {
        float qa[8], kb[8];
        #pragma unroll
        for (int i = 0; i < 8; i++) qa[i] = Qs[k * CHUNK + tx + 16 * i];
        #pragma unroll
        for (int j = 0; j < 8; j++) kb[j] = Ks[k * CHUNK + ty + 16 * j];
        #pragma unroll
        for (int j = 0; j < 8; j++)
            #pragma unroll
            for (int i = 0; i < 8; i++) acc[i][j] = fmaf(qa[i], kb[j], acc[i][j]);
    }
    #pragma unroll
    for (int j = 0; j < 8; j++) {
        int t = ty + 16 * j;
        #pragma unroll
        for (int i = 0; i < 8; i++) {
            int n = tx + 16 * i;
            As[t * 129 + n] = (t <= n) ? acc[i][j] : 0.f;
        }
    }
    __syncthreads();  // all Ks reads done; safe to overlay

    float* Vs = Ks;                 // [t][v], stride 65
    float* Ss = Ks + CHUNK * DVA;   // [v][m], stride 128 (row v=64 is z)
    for (int idx = tid; idx < DVV * CHUNK; idx += 256) {
        int v = idx >> 7, t = idx & 127;
        Vs[t * DVA + v] = values[(h * DVV + v) * NSEQ + n0 + t];
    }
    for (int idx = tid; idx < DVA * MM; idx += 256)
        Ss[idx] = g_Sx[(long)(h * NCHUNK + c) * (DVA * MM) + idx];
    __syncthreads();

    float oacc[8][4], nsum[8];
    #pragma unroll
    for (int i = 0; i < 8; i++) {
        nsum[i] = 0.f;
        #pragma unroll
        for (int j = 0; j < 4; j++) oacc[i][j] = 0.f;
    }

    #pragma unroll 2
    for (int t = 0; t < CHUNK; t++) {       // intra-chunk: A @ Vaug
        float a[8], b[4];
        #pragma unroll
        for (int i = 0; i < 8; i++) a[i] = As[t * 129 + tx + 16 * i];
        #pragma unroll
        for (int j = 0; j < 4; j++) b[j] = Vs[t * DVA + ty + 16 * j];
        #pragma unroll
        for (int i = 0; i < 8; i++) nsum[i] += a[i];
        #pragma unroll
        for (int j = 0; j < 4; j++)
            #pragma unroll
            for (int i = 0; i < 8; i++) oacc[i][j] = fmaf(a[i], b[j], oacc[i][j]);
    }

    #pragma unroll 2
    for (int m = 0; m < MM; m++) {          // inter-chunk: phiQ @ S_prefix
        float a[8], b[4];
        float sz = Ss[DVV * MM + m];
        #pragma unroll
        for (int i = 0; i < 8; i++) a[i] = Qs[m * CHUNK + tx + 16 * i];
        #pragma unroll
        for (int j = 0; j < 4; j++) b[j] = Ss[(ty + 16 * j) * MM + m];
        #pragma unroll
        for (int i = 0; i < 8; i++) nsum[i] = fmaf(a[i], sz, nsum[i]);
        #pragma unroll
        for (int j = 0; j < 4; j++)
            #pragma unroll
            for (int i = 0; i < 8; i++) oacc[i][j] = fmaf(a[i], b[j], oacc[i][j]);
    }

    #pragma unroll
    for (int j = 0; j < 4; j++) {
        int v = ty + 16 * j;
        #pragma unroll
        for (int i = 0; i < 8; i++) {
            int n = tx + 16 * i;
            outp[(h * DVV + v) * NSEQ + n0 + n] = oacc[i][j] / nsum[i];
        }
    }
}

// ---------------------------------------------------------------------------

static const int SM1_BYTES = (DD * CHUNK + MM * 65) * 4;        //  66048
static const int SM2_BYTES = (MM * 129 + CHUNK * DVP) * 4;      // 107520
static const int SM4_BYTES = SM4_FLOATS * 4;                    // 198144

extern "C" void kernel_launch(void* const* d_in, const int* in_sizes, int n_in,
                              void* d_out, int out_size) {
    const float* keys     = (const float*)d_in[0];
    const float* values   = (const float*)d_in[1];
    const float* queries  = (const float*)d_in[2];
    const float* features = (const float*)d_in[3];
    float* outp = (float*)d_out;

    // idempotent attribute sets (host-side, not stream-ordered; capture-safe)
    cudaFuncSetAttribute(phi_kernel, cudaFuncAttributeMaxDynamicSharedMemorySize, SM1_BYTES);
    cudaFuncSetAttribute(kv_kernel,  cudaFuncAttributeMaxDynamicSharedMemorySize, SM2_BYTES);
    cudaFuncSetAttribute(out_kernel, cudaFuncAttributeMaxDynamicSharedMemorySize, SM4_BYTES);

    phi_kernel<<<dim3(NCHUNK, HH, 2), 256, SM1_BYTES>>>(keys, queries, features);
    kv_kernel<<<dim3(NCHUNK, HH), 256, SM2_BYTES>>>(values);
    prefix_kernel<<<HH, 256>>>();
    out_kernel<<<dim3(NCHUNK, HH), 256, SM4_BYTES>>>(values, outp);
}

// round 2
// speedup vs baseline: 1.2513x; 1.2513x over previous
#include <cuda_runtime.h>
#include <cstdint>

// FAVOR causal linear attention, chunked. R2: out_kernel on tf32 mma.sync.
// Shapes: B=1, H=8, D=64, DV=64, N=2048, M=128. Chunk C=128, 16 chunks/head.
// out = (phi_q · KVcum) / (phi_q · Kcum), phi = relu(X·F^T); 1/sqrt(M) cancels.

#define HH     8
#define DD     64
#define DVV    64
#define NSEQ   2048
#define MM     128
#define CHUNK  128
#define NCHUNK 16
#define DVA    65
#define DVP    81

__device__ float g_phiQ[HH * MM * NSEQ];        // [h][m][n]
__device__ float g_phiK[HH * MM * NSEQ];        // [h][m][n]
__device__ float g_S [HH * NCHUNK * DVA * MM];  // [h][c][v][m]
__device__ float g_Sx[HH * NCHUNK * DVA * MM];  // exclusive prefix

// ---------------------------------------------------------------------------
// tf32 mma helpers
// ---------------------------------------------------------------------------
__device__ __forceinline__ uint32_t f2tf32(float x) {
    uint32_t r;
    asm("cvt.rna.tf32.f32 %0, %1;" : "=r"(r) : "f"(x));
    return r;
}
__device__ __forceinline__ void mma_tf32(float* c, const uint32_t* a, const uint32_t* b) {
    asm volatile(
        "mma.sync.aligned.m16n8k8.row.col.f32.tf32.tf32.f32 "
        "{%0,%1,%2,%3}, {%4,%5,%6,%7}, {%8,%9}, {%0,%1,%2,%3};"
        : "+f"(c[0]), "+f"(c[1]), "+f"(c[2]), "+f"(c[3])
        : "r"(a[0]), "r"(a[1]), "r"(a[2]), "r"(a[3]), "r"(b[0]), "r"(b[1]));
}

// ---------------------------------------------------------------------------
// Kernel 1: phi = relu(X^T @ F^T) -> [h][m][n]  (fp32 FFMA, unchanged)
// ---------------------------------------------------------------------------
extern "C" __global__ void phi_kernel(const float* __restrict__ keys,
                                      const float* __restrict__ queries,
                                      const float* __restrict__ features) {
    extern __shared__ float sm[];
    float* Xs = sm;               // [DD][CHUNK]
    float* Fs = sm + DD * CHUNK;  // [MM][65]

    int c = blockIdx.x, h = blockIdx.y;
    const float* X  = blockIdx.z ? queries : keys;
    float*     outp = blockIdx.z ? g_phiQ : g_phiK;
    int n0 = c * CHUNK, tid = threadIdx.x;

    for (int idx = tid; idx < DD * CHUNK; idx += 256) {
        int d = idx >> 7, n = idx & 127;
        Xs[d * CHUNK + n] = X[(h * DD + d) * NSEQ + n0 + n];
    }
    for (int idx = tid; idx < MM * DD; idx += 256) {
        int m = idx >> 6, d = idx & 63;
        Fs[m * 65 + d] = features[idx];
    }
    __syncthreads();

    int tx = tid & 15, ty = tid >> 4;
    float acc[8][8];
    #pragma unroll
    for (int i = 0; i < 8; i++)
        #pragma unroll
        for (int j = 0; j < 8; j++) acc[i][j] = 0.f;

    #pragma unroll 4
    for (int d = 0; d < DD; d++) {
        float a[8], b[8];
        #pragma unroll
        for (int j = 0; j < 8; j++) a[j] = Fs[(ty + 16 * j) * 65 + d];
        #pragma unroll
        for (int i = 0; i < 8; i++) b[i] = Xs[d * CHUNK + tx + 16 * i];
        #pragma unroll
        for (int j = 0; j < 8; j++)
            #pragma unroll
            for (int i = 0; i < 8; i++) acc[i][j] = fmaf(a[j], b[i], acc[i][j]);
    }

    #pragma unroll
    for (int j = 0; j < 8; j++) {
        int m = ty + 16 * j;
        #pragma unroll
        for (int i = 0; i < 8; i++) {
            int n = tx + 16 * i;
            outp[(h * MM + m) * NSEQ + n0 + n] = fmaxf(acc[i][j], 0.f);
        }
    }
}

// ---------------------------------------------------------------------------
// Kernel 2: S_c[v][m] = sum_t phiK[m][t] * Vaug[t][v]   (unchanged)
// ---------------------------------------------------------------------------
extern "C" __global__ void kv_kernel(const float* __restrict__ values) {
    extern __shared__ float sm[];
    float* Ks = sm;              // [MM][129]
    float* Vs = sm + MM * 129;   // [CHUNK][DVP]

    int c = blockIdx.x, h = blockIdx.y, n0 = c * CHUNK, tid = threadIdx.x;

    for (int idx = tid; idx < MM * CHUNK; idx += 256) {
        int m = idx >> 7, t = idx & 127;
        Ks[m * 129 + t] = g_phiK[(h * MM + m) * NSEQ + n0 + t];
    }
    for (int idx = tid; idx < CHUNK * DVP; idx += 256)
        Vs[idx] = ((idx % DVP) == DVV) ? 1.0f : 0.0f;
    __syncthreads();
    for (int idx = tid; idx < DVV * CHUNK; idx += 256) {
        int v = idx >> 7, t = idx & 127;
        Vs[t * DVP + v] = values[(h * DVV + v) * NSEQ + n0 + t];
    }
    __syncthreads();

    int tx = tid & 15, ty = tid >> 4;
    float acc[8][5];
    #pragma unroll
    for (int i = 0; i < 8; i++)
        #pragma unroll
        for (int j = 0; j < 5; j++) acc[i][j] = 0.f;

    #pragma unroll 2
    for (int t = 0; t < CHUNK; t++) {
        float a[8], b[5];
        #pragma unroll
        for (int i = 0; i < 8; i++) a[i] = Ks[(tx + 16 * i) * 129 + t];
        #pragma unroll
        for (int j = 0; j < 5; j++) b[j] = Vs[t * DVP + ty + 16 * j];
        #pragma unroll
        for (int j = 0; j < 5; j++)
            #pragma unroll
            for (int i = 0; i < 8; i++) acc[i][j] = fmaf(a[i], b[j], acc[i][j]);
    }

    long base = (long)(h * NCHUNK + c) * (DVA * MM);
    #pragma unroll
    for (int j = 0; j < 5; j++) {
        int v = ty + 16 * j;
        if (v < DVA) {
            #pragma unroll
            for (int i = 0; i < 8; i++)
                g_S[base + (long)v * MM + tx + 16 * i] = acc[i][j];
        }
    }
}

// ---------------------------------------------------------------------------
// Kernel 3: exclusive prefix over 16 chunks. grid (H, 4) now (4x parallelism).
// Loads are run-independent -> 16-deep MLP per element.
// ---------------------------------------------------------------------------
extern "C" __global__ void prefix_kernel() {
    const int E = DVA * MM;           // 8320
    const int PART = (E + 3) / 4;     // 2080
    int h = blockIdx.x;
    int e0 = blockIdx.y * PART;
    int e1 = min(E, e0 + PART);
    for (int e = e0 + (int)threadIdx.x; e < e1; e += 256) {
        float run = 0.f;
        #pragma unroll
        for (int cc = 0; cc < NCHUNK; cc++) {
            long base = (long)(h * NCHUNK + cc) * E + e;
            g_Sx[base] = run;
            run += g_S[base];
        }
    }
}

// ---------------------------------------------------------------------------
// Kernel 4 (tf32 mma): per-chunk output.
//   phase a: A[n][t] = sum_m Q[m][n] K[m][t], causal masked, stored tf32.
//   phase b: O[n][v] = [A | Q](n, k=256) @ Bv(k=256, v=72)
//            Bv rows 0..127: [V(t,v) | 1 | 0-pad]; rows 128..255: [S(v,m)^T | z | 0]
//            column 64 of O == normalizer. O[v<64] /= O[64].
// grid (16, 8), block 256 (8 warps), smem 212992 B.
// ---------------------------------------------------------------------------
#define SQ   136   // stride of Qs[m][n], Ks[m][t], As[n][t]
#define SB   72    // stride of Bv[k][v]
#define SO   132   // stride of Os[v][n]
#define R_QS 0
#define R_AS (128 * SQ)            // 17408
#define R_2  (2 * 128 * SQ)        // 34816 : Ks -> Bv -> Os
#define SM4_U32 (R_2 + 256 * SB)   // 34816 + 18432 = 53248 u32 = 212992 B

extern "C" __global__ void __launch_bounds__(256, 1)
out_kernel(const float* __restrict__ values, float* __restrict__ outp) {
    extern __shared__ uint32_t smu[];
    uint32_t* Qs = smu + R_QS;   // tf32 phiQ[m][n]
    uint32_t* As = smu + R_AS;   // tf32 A[n][t]
    uint32_t* R2 = smu + R_2;    // Ks / Bv / Os

    int c = blockIdx.x, h = blockIdx.y, n0 = c * CHUNK;
    int tid = threadIdx.x, warp = tid >> 5, lane = tid & 31;
    int lq = lane >> 2, lr = lane & 3;   // quad row / col-in-quad

    // ---- fill Qs, Ks (tf32) ----
    {
        uint32_t* Ks = R2;
        for (int idx = tid; idx < MM * CHUNK; idx += 256) {
            int m = idx >> 7, n = idx & 127;
            Qs[m * SQ + n] = f2tf32(g_phiQ[(h * MM + m) * NSEQ + n0 + n]);
            Ks[m * SQ + n] = f2tf32(g_phiK[(h * MM + m) * NSEQ + n0 + n]);
        }
    }
    __syncthreads();

    // ---- phase a: A = Q^T K over m.  warp tile 32(n) x 64(t) ----
    {
        const uint32_t* Ks = R2;
        int nw = (warp >> 1) * 32;     // n offset
        int tw = (warp & 1) * 64;      // t offset
        float acc[2][8][4];
        #pragma unroll
        for (int mi = 0; mi < 2; mi++)
            #pragma unroll
            for (int ni = 0; ni < 8; ni++)
                #pragma unroll
                for (int r = 0; r < 4; r++) acc[mi][ni][r] = 0.f;

        #pragma unroll 2
        for (int k0 = 0; k0 < MM; k0 += 8) {
            uint32_t af[2][4], bf[8][2];
            #pragma unroll
            for (int mi = 0; mi < 2; mi++) {
                int n = nw + mi * 16 + lq;
                af[mi][0] = Qs[(k0 + lr) * SQ + n];
                af[mi][1] = Qs[(k0 + lr) * SQ + n + 8];
                af[mi][2] = Qs[(k0 + 4 + lr) * SQ + n];
                af[mi][3] = Qs[(k0 + 4 + lr) * SQ + n + 8];
            }
            #pragma unroll
            for (int ni = 0; ni < 8; ni++) {
                int t = tw + ni * 8 + lq;
                bf[ni][0] = Ks[(k0 + lr) * SQ + t];
                bf[ni][1] = Ks[(k0 + 4 + lr) * SQ + t];
            }
            #pragma unroll
            for (int mi = 0; mi < 2; mi++)
                #pragma unroll
                for (int ni = 0; ni < 8; ni++)
                    mma_tf32(acc[mi][ni], af[mi], bf[ni]);
        }

        // causal mask + store tf32 A[n][t]
        #pragma unroll
        for (int mi = 0; mi < 2; mi++) {
            #pragma unroll
            for (int ni = 0; ni < 8; ni++) {
                int n = nw + mi * 16 + lq;
                int t = tw + ni * 8 + 2 * lr;
                As[n * SQ + t]           = f2tf32(t     <= n     ? acc[mi][ni][0] : 0.f);
                As[n * SQ + t + 1]       = f2tf32(t + 1 <= n     ? acc[mi][ni][1] : 0.f);
                As[(n + 8) * SQ + t]     = f2tf32(t     <= n + 8 ? acc[mi][ni][2] : 0.f);
                As[(n + 8) * SQ + t + 1] = f2tf32(t + 1 <= n + 8 ? acc[mi][ni][3] : 0.f);
            }
        }
    }
    __syncthreads();   // Ks reads done; overlay with Bv

    // ---- fill Bv[256][72] ----
    {
        uint32_t* Bv = R2;
        const uint32_t ONE = f2tf32(1.0f);
        // rows 0..127: V augmented
        for (int idx = tid; idx < DVV * CHUNK; idx += 256) {
            int v = idx >> 7, t = idx & 127;
            Bv[t * SB + v] = f2tf32(values[(h * DVV + v) * NSEQ + n0 + t]);
        }
        for (int idx = tid; idx < CHUNK * 8; idx += 256) {      // v = 64..71
            int t = idx >> 3, v = 64 + (idx & 7);
            Bv[t * SB + v] = (v == DVV) ? ONE : 0u;
        }
        // rows 128..255: S prefix transposed (+ z at v=64)
        long sb = (long)(h * NCHUNK + c) * (DVA * MM);
        for (int idx = tid; idx < DVA * MM; idx += 256) {
            int v = idx >> 7, m = idx & 127;
            Bv[(128 + m) * SB + v] = f2tf32(g_Sx[sb + idx]);
        }
        for (int idx = tid; idx < MM * 7; idx += 256) {         // v = 65..71
            int m = idx / 7, v = 65 + idx % 7;
            Bv[(128 + m) * SB + v] = 0u;
        }
    }
    __syncthreads();

    // ---- phase b: O[128n][72v] = [A | Q] @ Bv.  warp tile 16(n) x 72(v) ----
    float accB[9][4];
    #pragma unroll
    for (int vi = 0; vi < 9; vi++)
        #pragma unroll
        for (int r = 0; r < 4; r++) accB[vi][r] = 0.f;

    {
        const uint32_t* Bv = R2;
        int n = warp * 16 + lq;
        // part 1: k = t (A operand = As[n][t], row-major)
        #pragma unroll 2
        for (int k0 = 0; k0 < 128; k0 += 8) {
            uint32_t af[4];
            af[0] = As[n * SQ + k0 + lr];
            af[1] = As[(n + 8) * SQ + k0 + lr];
            af[2] = As[n * SQ + k0 + 4 + lr];
            af[3] = As[(n + 8) * SQ + k0 + 4 + lr];
            #pragma unroll
            for (int vi = 0; vi < 9; vi++) {
                uint32_t bf[2];
                int v = vi * 8 + lq;
                bf[0] = Bv[(k0 + lr) * SB + v];
                bf[1] = Bv[(k0 + 4 + lr) * SB + v];
                mma_tf32(accB[vi], af, bf);
            }
        }
        // part 2: k = m (A operand = Q[n][m] = Qs[m][n])
        #pragma unroll 2
        for (int k0 = 0; k0 < 128; k0 += 8) {
            uint32_t af[4];
            af[0] = Qs[(k0 + lr) * SQ + n];
            af[1] = Qs[(k0 + lr) * SQ + n + 8];
            af[2] = Qs[(k0 + 4 + lr) * SQ + n];
            af[3] = Qs[(k0 + 4 + lr) * SQ + n + 8];
            #pragma unroll
            for (int vi = 0; vi < 9; vi++) {
                uint32_t bf[2];
                int v = vi * 8 + lq;
                bf[0] = Bv[(128 + k0 + lr) * SB + v];
                bf[1] = Bv[(128 + k0 + 4 + lr) * SB + v];
                mma_tf32(accB[vi], af, bf);
            }
        }
    }
    __syncthreads();   // Bv reads done; overlay with Os

    // ---- epilogue: divide by norm (col 64), stage Os[v][n], coalesced store ----
    {
        uint32_t* Os = R2;
        float nlo = __shfl_sync(0xffffffffu, accB[8][0], lane & ~3);
        float nhi = __shfl_sync(0xffffffffu, accB[8][2], lane & ~3);
        float rlo = 1.f / nlo, rhi = 1.f / nhi;
        int nloc = warp * 16 + lq;
        #pragma unroll
        for (int vi = 0; vi < 8; vi++) {
            int v = vi * 8 + 2 * lr;
            Os[v * SO + nloc]           = __float_as_uint(accB[vi][0] * rlo);
            Os[(v + 1) * SO + nloc]     = __float_as_uint(accB[vi][1] * rlo);
            Os[v * SO + nloc + 8]       = __float_as_uint(accB[vi][2] * rhi);
            Os[(v + 1) * SO + nloc + 8] = __float_as_uint(accB[vi][3] * rhi);
        }
        __syncthreads();
        for (int idx = tid; idx < DVV * CHUNK; idx += 256) {
            int v = idx >> 7, nn = idx & 127;
            outp[(h * DVV + v) * NSEQ + n0 + nn] = __uint_as_float(Os[v * SO + nn]);
        }
    }
}

// ---------------------------------------------------------------------------

static const int SM1_BYTES = (DD * CHUNK + MM * 65) * 4;
static const int SM2_BYTES = (MM * 129 + CHUNK * DVP) * 4;
static const int SM4_BYTES = SM4_U32 * 4;   // 212992

extern "C" void kernel_launch(void* const* d_in, const int* in_sizes, int n_in,
                              void* d_out, int out_size) {
    const float* keys     = (const float*)d_in[0];
    const float* values   = (const float*)d_in[1];
    const float* queries  = (const float*)d_in[2];
    const float* features = (const float*)d_in[3];
    float* outp = (float*)d_out;

    cudaFuncSetAttribute(phi_kernel, cudaFuncAttributeMaxDynamicSharedMemorySize, SM1_BYTES);
    cudaFuncSetAttribute(kv_kernel,  cudaFuncAttributeMaxDynamicSharedMemorySize, SM2_BYTES);
    cudaFuncSetAttribute(out_kernel, cudaFuncAttributeMaxDynamicSharedMemorySize, SM4_BYTES);

    phi_kernel<<<dim3(NCHUNK, HH, 2), 256, SM1_BYTES>>>(keys, queries, features);
    kv_kernel<<<dim3(NCHUNK, HH), 256, SM2_BYTES>>>(values);
    prefix_kernel<<<dim3(HH, 4), 256>>>();
    out_kernel<<<dim3(NCHUNK, HH), 256, SM4_BYTES>>>(values, outp);
}

// round 3
// speedup vs baseline: 2.7659x; 2.2105x over previous
#include <cuda_runtime.h>
#include <cstdint>

// FAVOR causal linear attention — R3: single fused kernel, flag-synced prefix.
// B=1,H=8,D=64,DV=64,N=2048,M=128. Chunk C=128, grid(16,8)=128 blocks (1 wave).
// out = (phiQ·KVcum)/(phiQ·Kcum), phi = relu(X·F^T); 1/sqrt(M) cancels.
// phi computed with fp32 accuracy via 3-term tf32 split (Fh·Xh + Fh·Xl + Fl·Xh).

#define HH     8
#define DD     64
#define DVV    64
#define NSEQ   2048
#define MM     128
#define CHUNK  128
#define NCHUNK 16
#define SQ     136   // stride: Qs/Ks [m][.] , X [d][n]
#define SV     72    // stride: Vs [t][v], Ss [m][v]
#define SF     68    // stride: F split [m][d]
#define SOS    132   // stride: Os [v][n]

// chunk states + flags (device globals; flags zero-init, monotonically +1/launch)
__device__ float g_S[HH * NCHUNK * MM * 65];   // [h][c][m*65+v], v=64 is z
__device__ int   g_flag[HH * NCHUNK];

__device__ __forceinline__ uint32_t f2tf32(float x) {
    uint32_t r;
    asm("cvt.rna.tf32.f32 %0, %1;" : "=r"(r) : "f"(x));
    return r;
}
__device__ __forceinline__ void mma_tf32(float* c, const uint32_t* a, const uint32_t* b) {
    asm volatile(
        "mma.sync.aligned.m16n8k8.row.col.f32.tf32.tf32.f32 "
        "{%0,%1,%2,%3}, {%4,%5,%6,%7}, {%8,%9}, {%0,%1,%2,%3};"
        : "+f"(c[0]), "+f"(c[1]), "+f"(c[2]), "+f"(c[3])
        : "r"(a[0]), "r"(a[1]), "r"(a[2]), "r"(a[3]), "r"(b[0]), "r"(b[1]));
}
__device__ __forceinline__ int ld_acquire(const int* p) {
    int v;
    asm volatile("ld.acquire.gpu.b32 %0, [%1];" : "=r"(v) : "l"(p) : "memory");
    return v;
}

// load X chunk [64d][128n] from global, split into tf32 hi/lo tiles [d][SQ]
__device__ __forceinline__ void fill_x(const float* __restrict__ Xg,
                                       uint32_t* Xh, uint32_t* Xl, int tid) {
    for (int idx = tid; idx < DD * CHUNK; idx += 256) {
        int d = idx >> 7, n = idx & 127;
        float x = Xg[d * NSEQ + n];
        uint32_t hi = f2tf32(x);
        Xh[d * SQ + n] = hi;
        Xl[d * SQ + n] = f2tf32(x - __uint_as_float(hi));
    }
}

// phi = relu(F @ X) with 3-term compensation; warp tile 16m x 128n.
// Internal pre-store __syncthreads: for the Q pass, dst overlays the F tiles.
__device__ __forceinline__ void phi_pass(const uint32_t* Fh, const uint32_t* Fl,
                                         const uint32_t* Xh, const uint32_t* Xl,
                                         uint32_t* dst, int warp, int g, int cc) {
    int mb = warp * 16;
    float acc[16][4];
    #pragma unroll
    for (int ni = 0; ni < 16; ni++)
        #pragma unroll
        for (int r = 0; r < 4; r++) acc[ni][r] = 0.f;

    #pragma unroll 1
    for (int k0 = 0; k0 < DD; k0 += 8) {
        uint32_t ah[4], al[4];
        ah[0] = Fh[(mb + g) * SF + k0 + cc];
        ah[1] = Fh[(mb + g + 8) * SF + k0 + cc];
        ah[2] = Fh[(mb + g) * SF + k0 + 4 + cc];
        ah[3] = Fh[(mb + g + 8) * SF + k0 + 4 + cc];
        al[0] = Fl[(mb + g) * SF + k0 + cc];
        al[1] = Fl[(mb + g + 8) * SF + k0 + cc];
        al[2] = Fl[(mb + g) * SF + k0 + 4 + cc];
        al[3] = Fl[(mb + g + 8) * SF + k0 + 4 + cc];
        #pragma unroll
        for (int ni = 0; ni < 16; ni++) {
            uint32_t bh[2], bl[2];
            bh[0] = Xh[(k0 + cc) * SQ + ni * 8 + g];
            bh[1] = Xh[(k0 + 4 + cc) * SQ + ni * 8 + g];
            bl[0] = Xl[(k0 + cc) * SQ + ni * 8 + g];
            bl[1] = Xl[(k0 + 4 + cc) * SQ + ni * 8 + g];
            mma_tf32(acc[ni], ah, bh);
            mma_tf32(acc[ni], ah, bl);
            mma_tf32(acc[ni], al, bh);
        }
    }
    __syncthreads();   // all warps done reading F/X before dst may overlay F
    #pragma unroll
    for (int ni = 0; ni < 16; ni++) {
        int n = ni * 8 + 2 * cc;
        uint2 p0, p1;
        p0.x = f2tf32(fmaxf(acc[ni][0], 0.f));
        p0.y = f2tf32(fmaxf(acc[ni][1], 0.f));
        p1.x = f2tf32(fmaxf(acc[ni][2], 0.f));
        p1.y = f2tf32(fmaxf(acc[ni][3], 0.f));
        *(uint2*)&dst[(mb + g) * SQ + n]     = p0;
        *(uint2*)&dst[(mb + g + 8) * SQ + n] = p1;
    }
}

// smem layout (u32 indices)
#define R_KS   (128 * SQ)          // 17408
#define R_TMP  (2 * 128 * SQ)      // 34816
#define SM_U32 (R_TMP + 2 * 64 * SQ)   // 52224 u32 = 208896 B

extern "C" __global__ void __launch_bounds__(256, 1)
favor_kernel(const float* __restrict__ keys, const float* __restrict__ values,
             const float* __restrict__ queries, const float* __restrict__ features,
             float* __restrict__ outp) {
    extern __shared__ uint32_t smu[];
    uint32_t* Qs = smu;                      // final phiQ tf32 [m][n]   (holds F split first)
    uint32_t* Fh = smu;                      // [128][68]
    uint32_t* Fl = smu + 128 * SF;
    uint32_t* Ks = smu + R_KS;               // phiK tf32 [m][t]; later Ss [m][v]
    uint32_t* Ss = smu + R_KS;
    uint32_t* Xh = smu + R_TMP;              // X split [d][n]
    uint32_t* Xl = smu + R_TMP + 64 * SQ;
    uint32_t* Vs = smu + R_TMP;              // Vaug tf32 [t][72]
    uint32_t* Os = smu + R_TMP;              // out staging [v][132]

    int c = blockIdx.x, h = blockIdx.y, n0 = c * CHUNK;
    int tid = threadIdx.x, warp = tid >> 5, lane = tid & 31;
    int g = lane >> 2, cc = lane & 3;
    int fb = h * NCHUNK;
    int s1 = g_flag[fb + c] + 1;   // epoch baseline (own flag, written only by self)

    // ---- P0: features split -> Qs region ----
    for (int idx = tid; idx < MM * DD; idx += 256) {
        int m = idx >> 6, d = idx & 63;
        float f = features[idx];
        uint32_t hi = f2tf32(f);
        Fh[m * SF + d] = hi;
        Fl[m * SF + d] = f2tf32(f - __uint_as_float(hi));
    }
    // ---- P1: phiK ----
    fill_x(keys + (h * DD) * NSEQ + n0, Xh, Xl, tid);
    __syncthreads();
    phi_pass(Fh, Fl, Xh, Xl, Ks, warp, g, cc);
    __syncthreads();
    // ---- P2: phiQ (store overlays F; phi_pass syncs internally before store) ----
    fill_x(queries + (h * DD) * NSEQ + n0, Xh, Xl, tid);
    __syncthreads();
    phi_pass(Fh, Fl, Xh, Xl, Qs, warp, g, cc);
    __syncthreads();

    // ---- P3: Vaug tf32 [t][72] (col 64 = 1, 65..71 = 0) ----
    for (int idx = tid; idx < DVV * CHUNK; idx += 256) {
        int v = idx >> 7, t = idx & 127;
        Vs[t * SV + v] = f2tf32(values[(h * DVV + v) * NSEQ + n0 + t]);
    }
    {
        const uint32_t ONE = f2tf32(1.0f);
        for (int idx = tid; idx < CHUNK * 8; idx += 256) {
            int t = idx >> 3, v = 64 + (idx & 7);
            Vs[t * SV + v] = (v == DVV) ? ONE : 0u;
        }
    }
    __syncthreads();

    // ---- S_c[m][v] = sum_t phiK[m][t] * Vaug[t][v]  (tf32 mma) -> global ----
    {
        int mb = warp * 16;
        float sa[9][4];
        #pragma unroll
        for (int vi = 0; vi < 9; vi++)
            #pragma unroll
            for (int r = 0; r < 4; r++) sa[vi][r] = 0.f;
        #pragma unroll 1
        for (int k0 = 0; k0 < CHUNK; k0 += 8) {
            uint32_t af[4];
            af[0] = Ks[(mb + g) * SQ + k0 + cc];
            af[1] = Ks[(mb + g + 8) * SQ + k0 + cc];
            af[2] = Ks[(mb + g) * SQ + k0 + 4 + cc];
            af[3] = Ks[(mb + g + 8) * SQ + k0 + 4 + cc];
            #pragma unroll
            for (int vi = 0; vi < 9; vi++) {
                uint32_t bf[2];
                bf[0] = Vs[(k0 + cc) * SV + vi * 8 + g];
                bf[1] = Vs[(k0 + 4 + cc) * SV + vi * 8 + g];
                mma_tf32(sa[vi], af, bf);
            }
        }
        float* Sg = g_S + (long)(fb + c) * (MM * 65);
        #pragma unroll
        for (int vi = 0; vi < 9; vi++) {
            int v0 = vi * 8 + 2 * cc;
            if (v0 < 65) {
                Sg[(mb + g) * 65 + v0]     = sa[vi][0];
                Sg[(mb + g + 8) * 65 + v0] = sa[vi][2];
            }
            if (v0 + 1 < 65) {
                Sg[(mb + g) * 65 + v0 + 1]     = sa[vi][1];
                Sg[(mb + g + 8) * 65 + v0 + 1] = sa[vi][3];
            }
        }
    }
    __threadfence();
    __syncthreads();
    if (tid == 0) atomicAdd(&g_flag[fb + c], 1);   // release (fence above)

    // ---- P4: A = phiQ^T phiK, causal-masked, kept in registers as A-frags ----
    uint32_t aA[16][4];
    {
        int wb = warp * 16;
        float acc[16][4];
        #pragma unroll
        for (int ti = 0; ti < 16; ti++)
            #pragma unroll
            for (int r = 0; r < 4; r++) acc[ti][r] = 0.f;
        #pragma unroll 1
        for (int k0 = 0; k0 < MM; k0 += 8) {
            uint32_t af[4];
            af[0] = Qs[(k0 + cc) * SQ + wb + g];
            af[1] = Qs[(k0 + cc) * SQ + wb + g + 8];
            af[2] = Qs[(k0 + 4 + cc) * SQ + wb + g];
            af[3] = Qs[(k0 + 4 + cc) * SQ + wb + g + 8];
            #pragma unroll
            for (int ti = 0; ti < 16; ti++) {
                uint32_t bf[2];
                bf[0] = Ks[(k0 + cc) * SQ + ti * 8 + g];
                bf[1] = Ks[(k0 + 4 + cc) * SQ + ti * 8 + g];
                mma_tf32(acc[ti], af, bf);
            }
        }
        // mask + C-frag -> A-frag conversion (shuffles), tf32 round
        int srcA = (g << 2) | (cc >> 1);
        int srcB = srcA + 2;
        bool odd = cc & 1;
        int nlo = wb + g, nhi = wb + g + 8;
        #pragma unroll
        for (int ti = 0; ti < 16; ti++) {
            int t0 = ti * 8 + 2 * cc;
            float m0 = (t0     <= nlo) ? acc[ti][0] : 0.f;
            float m1 = (t0 + 1 <= nlo) ? acc[ti][1] : 0.f;
            float m2 = (t0     <= nhi) ? acc[ti][2] : 0.f;
            float m3 = (t0 + 1 <= nhi) ? acc[ti][3] : 0.f;
            float x0 = __shfl_sync(0xffffffffu, m0, srcA);
            float x1 = __shfl_sync(0xffffffffu, m1, srcA);
            float x2 = __shfl_sync(0xffffffffu, m2, srcA);
            float x3 = __shfl_sync(0xffffffffu, m3, srcA);
            float y0 = __shfl_sync(0xffffffffu, m0, srcB);
            float y1 = __shfl_sync(0xffffffffu, m1, srcB);
            float y2 = __shfl_sync(0xffffffffu, m2, srcB);
            float y3 = __shfl_sync(0xffffffffu, m3, srcB);
            aA[ti][0] = f2tf32(odd ? x1 : x0);
            aA[ti][1] = f2tf32(odd ? x3 : x2);
            aA[ti][2] = f2tf32(odd ? y1 : y0);
            aA[ti][3] = f2tf32(odd ? y3 : y2);
        }
    }

    // ---- P5: wait for prior chunks, accumulate prefix state in registers ----
    float run[33];
    #pragma unroll
    for (int i = 0; i < 33; i++) run[i] = 0.f;
    if (tid == 0) {
        for (int pc = 0; pc < c; pc++)
            while (ld_acquire(&g_flag[fb + pc]) < s1) __nanosleep(64);
        __threadfence();
    }
    __syncthreads();
    for (int pc = 0; pc < c; pc++) {
        const float* Sg = g_S + (long)(fb + pc) * (MM * 65);
        #pragma unroll
        for (int i = 0; i < 33; i++) {
            int e = tid + 256 * i;
            if (e < MM * 65) run[i] += Sg[e];
        }
    }

    // ---- P6: Ss tf32 [m][72] overlays Ks (A & S done reading it) ----
    __syncthreads();
    {
        int e = tid, m = tid / 65, v = tid % 65;
        #pragma unroll
        for (int i = 0; i < 33; i++) {
            if (e < MM * 65) Ss[m * SV + v] = f2tf32(run[i]);
            e += 256; v += 61; m += 3;
            if (v >= 65) { v -= 65; m++; }
        }
        for (int idx = tid; idx < MM * 7; idx += 256) {
            int mm = idx / 7, vv = 65 + idx % 7;
            Ss[mm * SV + vv] = 0u;
        }
    }
    __syncthreads();

    // ---- P7: phase b. O[n][72v] = A@Vaug + phiQ^T@Ss. col 64 = normalizer ----
    float accB[9][4];
    #pragma unroll
    for (int vi = 0; vi < 9; vi++)
        #pragma unroll
        for (int r = 0; r < 4; r++) accB[vi][r] = 0.f;
    {
        int wb = warp * 16;
        #pragma unroll
        for (int kb = 0; kb < 16; kb++) {          // intra-chunk: k = t
            #pragma unroll
            for (int vi = 0; vi < 9; vi++) {
                uint32_t bf[2];
                bf[0] = Vs[(kb * 8 + cc) * SV + vi * 8 + g];
                bf[1] = Vs[(kb * 8 + 4 + cc) * SV + vi * 8 + g];
                mma_tf32(accB[vi], aA[kb], bf);
            }
        }
        #pragma unroll 1
        for (int k0 = 0; k0 < MM; k0 += 8) {       // inter-chunk: k = m
            uint32_t qa[4];
            qa[0] = Qs[(k0 + cc) * SQ + wb + g];
            qa[1] = Qs[(k0 + cc) * SQ + wb + g + 8];
            qa[2] = Qs[(k0 + 4 + cc) * SQ + wb + g];
            qa[3] = Qs[(k0 + 4 + cc) * SQ + wb + g + 8];
            #pragma unroll
            for (int vi = 0; vi < 9; vi++) {
                uint32_t bf[2];
                bf[0] = Ss[(k0 + cc) * SV + vi * 8 + g];
                bf[1] = Ss[(k0 + 4 + cc) * SV + vi * 8 + g];
                mma_tf32(accB[vi], qa, bf);
            }
        }
    }

    // ---- P8: epilogue: divide by norm, stage, coalesced store ----
    {
        float nlo = __shfl_sync(0xffffffffu, accB[8][0], lane & ~3);
        float nhi = __shfl_sync(0xffffffffu, accB[8][2], lane & ~3);
        float rlo = 1.f / nlo, rhi = 1.f / nhi;
        int wb = warp * 16;
        __syncthreads();   // Vs dead -> Os overlays
        #pragma unroll
        for (int vi = 0; vi < 8; vi++) {
            int v = vi * 8 + 2 * cc;
            Os[v * SOS + wb + g]           = __float_as_uint(accB[vi][0] * rlo);
            Os[(v + 1) * SOS + wb + g]     = __float_as_uint(accB[vi][1] * rlo);
            Os[v * SOS + wb + g + 8]       = __float_as_uint(accB[vi][2] * rhi);
            Os[(v + 1) * SOS + wb + g + 8] = __float_as_uint(accB[vi][3] * rhi);
        }
        __syncthreads();
        for (int idx = tid; idx < DVV * CHUNK; idx += 256) {
            int v = idx >> 7, n = idx & 127;
            outp[(h * DVV + v) * NSEQ + n0 + n] = __uint_as_float(Os[v * SOS + n]);
        }
    }
}

static const int SM_BYTES = SM_U32 * 4;   // 208896

extern "C" void kernel_launch(void* const* d_in, const int* in_sizes, int n_in,
                              void* d_out, int out_size) {
    const float* keys     = (const float*)d_in[0];
    const float* values   = (const float*)d_in[1];
    const float* queries  = (const float*)d_in[2];
    const float* features = (const float*)d_in[3];
    float* outp = (float*)d_out;

    cudaFuncSetAttribute(favor_kernel, cudaFuncAttributeMaxDynamicSharedMemorySize, SM_BYTES);
    favor_kernel<<<dim3(NCHUNK, HH), 256, SM_BYTES>>>(keys, values, queries, features, outp);
}

// round 4
// speedup vs baseline: 2.8412x; 1.0272x over previous
#include <cuda_runtime.h>
#include <cstdint>

// FAVOR causal linear attention — R4: fused kernel + ldmatrix fragment loads.
// B=1,H=8,D=64,DV=64,N=2048,M=128. Chunk C=128, grid(16,8)=128 blocks (1 wave).
// Layouts ([row][k-contiguous], ldmatrix-ready):
//   F[m][d]@68, Xt[n][d]@68, Qt[n][m]@132, Kt[t][m]@132, Vt[v][t]@132 (80 rows,
//   row64=ones), Ssl[v][m]@132 (80 rows). Regions: A=F->Qt, B=Xt->Vt->Os, C=Kt->Ssl.

#define HH     8
#define DD     64
#define DVV    64
#define NSEQ   2048
#define MM     128
#define CHUNK  128
#define NCHUNK 16
#define SX     68
#define SW     132
#define OFF_B  17408
#define OFF_C  34816
#define SM_U32 51712   // 206848 bytes

__device__ float g_S[HH * NCHUNK * 65 * MM];   // [h][c][v*128+m], v=64 is z
__device__ int   g_flag[HH * NCHUNK];

__device__ __forceinline__ uint32_t f2tf32(float x) {
    uint32_t r;
    asm("cvt.rna.tf32.f32 %0, %1;" : "=r"(r) : "f"(x));
    return r;
}
__device__ __forceinline__ void mma_tf32(float* c, const uint32_t* a, const uint32_t* b) {
    asm volatile(
        "mma.sync.aligned.m16n8k8.row.col.f32.tf32.tf32.f32 "
        "{%0,%1,%2,%3}, {%4,%5,%6,%7}, {%8,%9}, {%0,%1,%2,%3};"
        : "+f"(c[0]), "+f"(c[1]), "+f"(c[2]), "+f"(c[3])
        : "r"(a[0]), "r"(a[1]), "r"(a[2]), "r"(a[3]), "r"(b[0]), "r"(b[1]));
}
__device__ __forceinline__ int ld_acquire(const int* p) {
    int v;
    asm volatile("ld.acquire.gpu.b32 %0, [%1];" : "=r"(v) : "l"(p) : "memory");
    return v;
}
// 16-row x 8-tf32-col fragment via ldmatrix (b16 view). As A-frag: r[0..3].
// As two B-frags (rows r0..r0+7 / r0+8..r0+15): {r0,r2} and {r1,r3}.
__device__ __forceinline__ void ldsm4(uint32_t r[4], uint32_t sbase,
                                      int row0, int k0, int stride, int lane) {
    uint32_t addr = sbase +
        (uint32_t)(((row0 + (lane & 7) + (lane & 8)) * stride + k0 + ((lane & 16) >> 2)) * 4);
    asm volatile("ldmatrix.sync.aligned.m8n8.x4.shared.b16 {%0,%1,%2,%3}, [%4];"
                 : "=r"(r[0]), "=r"(r[1]), "=r"(r[2]), "=r"(r[3]) : "r"(addr));
}

// phi = relu(X·F^T) transposed: C[n][m] = sum_d Xt[n][d] F[m][d], 3-term tf32.
__device__ __forceinline__ void phi_mma(uint32_t sX, uint32_t sXl, uint32_t sF,
                                        uint32_t sFl, int wb, int lane, float acc[16][4]) {
    #pragma unroll
    for (int mi = 0; mi < 16; mi++)
        #pragma unroll
        for (int r = 0; r < 4; r++) acc[mi][r] = 0.f;
    #pragma unroll 2
    for (int k0 = 0; k0 < DD; k0 += 8) {
        uint32_t axh[4], axl[4];
        ldsm4(axh, sX,  wb, k0, SX, lane);
        ldsm4(axl, sXl, wb, k0, SX, lane);
        #pragma unroll
        for (int mj = 0; mj < 8; mj++) {
            uint32_t fh[4], fl[4];
            ldsm4(fh, sF,  mj * 16, k0, SX, lane);
            ldsm4(fl, sFl, mj * 16, k0, SX, lane);
            uint32_t b0[2] = {fh[0], fh[2]}, b1[2] = {fh[1], fh[3]};
            uint32_t c0[2] = {fl[0], fl[2]}, c1[2] = {fl[1], fl[3]};
            mma_tf32(acc[2 * mj],     axh, b0);
            mma_tf32(acc[2 * mj],     axl, b0);
            mma_tf32(acc[2 * mj],     axh, c0);
            mma_tf32(acc[2 * mj + 1], axh, b1);
            mma_tf32(acc[2 * mj + 1], axl, b1);
            mma_tf32(acc[2 * mj + 1], axh, c1);
        }
    }
}

__device__ __forceinline__ void store_phi(uint32_t* dst, int wb, int g, int cc,
                                          const float acc[16][4]) {
    #pragma unroll
    for (int mi = 0; mi < 16; mi++) {
        uint2 lo, hi;
        lo.x = f2tf32(fmaxf(acc[mi][0], 0.f));
        lo.y = f2tf32(fmaxf(acc[mi][1], 0.f));
        hi.x = f2tf32(fmaxf(acc[mi][2], 0.f));
        hi.y = f2tf32(fmaxf(acc[mi][3], 0.f));
        *(uint2*)&dst[(wb + g) * SW + mi * 8 + 2 * cc]     = lo;
        *(uint2*)&dst[(wb + g + 8) * SW + mi * 8 + 2 * cc] = hi;
    }
}

extern "C" __global__ void __launch_bounds__(256, 1)
favor_kernel(const float* __restrict__ keys, const float* __restrict__ values,
             const float* __restrict__ queries, const float* __restrict__ features,
             float* __restrict__ outp) {
    extern __shared__ uint32_t smu[];
    uint32_t sb = (uint32_t)__cvta_generic_to_shared(smu);
    const uint32_t sF  = sb;                       // Fh [128][68]
    const uint32_t sFl = sb + 8704u * 4;           // Fl
    const uint32_t sX  = sb + OFF_B * 4u;          // Xh [128][68]
    const uint32_t sXl = sb + (OFF_B + 8704u) * 4; // Xl
    const uint32_t sQt = sb;                       // Qt overlays F region
    const uint32_t sVt = sb + OFF_B * 4u;          // Vt overlays X region
    const uint32_t sKt = sb + OFF_C * 4u;          // Kt / Ssl
    uint32_t* Fh  = smu;
    uint32_t* Fl  = smu + 8704;
    uint32_t* Xh  = smu + OFF_B;
    uint32_t* Xl  = smu + OFF_B + 8704;
    uint32_t* Qt  = smu;
    uint32_t* Kt  = smu + OFF_C;
    uint32_t* Vt  = smu + OFF_B;
    uint32_t* Ssl = smu + OFF_C;
    uint32_t* Os  = smu + OFF_B;

    int c = blockIdx.x, h = blockIdx.y, n0 = c * CHUNK;
    int tid = threadIdx.x, warp = tid >> 5, lane = tid & 31;
    int g = lane >> 2, cc = lane & 3;
    int wb = warp * 16;
    int fb = h * NCHUNK;
    int s1 = g_flag[fb + c] + 1;   // epoch baseline

    // ---- fill F split [m][d] + Xt(keys) split [n][d] ----
    for (int idx = tid; idx < MM * DD; idx += 256) {
        int m = idx >> 6, d = idx & 63;
        float f = features[idx];
        uint32_t hi = f2tf32(f);
        Fh[m * SX + d] = hi;
        Fl[m * SX + d] = f2tf32(f - __uint_as_float(hi));
    }
    {
        const float* Xg = keys + (h * DD) * NSEQ + n0;
        for (int idx = tid; idx < DD * CHUNK; idx += 256) {
            int d = idx >> 7, n = idx & 127;
            float x = Xg[d * NSEQ + n];
            uint32_t hi = f2tf32(x);
            Xh[n * SX + d] = hi;
            Xl[n * SX + d] = f2tf32(x - __uint_as_float(hi));
        }
    }
    __syncthreads();

    // ---- phiK -> Kt[t][m] ----
    {
        float acc[16][4];
        phi_mma(sX, sXl, sF, sFl, wb, lane, acc);
        store_phi(Kt, wb, g, cc, acc);
    }
    __syncthreads();   // all warps done reading Xt before refill

    // ---- refill Xt with queries ----
    {
        const float* Xg = queries + (h * DD) * NSEQ + n0;
        for (int idx = tid; idx < DD * CHUNK; idx += 256) {
            int d = idx >> 7, n = idx & 127;
            float x = Xg[d * NSEQ + n];
            uint32_t hi = f2tf32(x);
            Xh[n * SX + d] = hi;
            Xl[n * SX + d] = f2tf32(x - __uint_as_float(hi));
        }
    }
    __syncthreads();

    // ---- phiQ; sync (F reads done); store Qt over F; fill Vt over Xt ----
    {
        float acc[16][4];
        phi_mma(sX, sXl, sF, sFl, wb, lane, acc);
        __syncthreads();
        store_phi(Qt, wb, g, cc, acc);
    }
    {
        const uint32_t ONE = f2tf32(1.0f);
        for (int idx = tid; idx < DVV * CHUNK; idx += 256) {
            int v = idx >> 7, t = idx & 127;
            Vt[v * SW + t] = f2tf32(values[(h * DVV + v) * NSEQ + n0 + t]);
        }
        for (int idx = tid; idx < 16 * CHUNK; idx += 256) {   // rows 64..79
            int v = 64 + (idx >> 7), t = idx & 127;
            Vt[v * SW + t] = (v == DVV) ? ONE : 0u;
        }
    }
    __syncthreads();

    // ---- S[m][v] = sum_t K[m][t] Vaug[t][v] -> g_S [v][m] fp32; release flag ----
    {
        float sa[9][4];
        #pragma unroll
        for (int vi = 0; vi < 9; vi++)
            #pragma unroll
            for (int r = 0; r < 4; r++) sa[vi][r] = 0.f;
        #pragma unroll 2
        for (int k0 = 0; k0 < CHUNK; k0 += 8) {
            uint32_t af[4];
            af[0] = Kt[(k0 + cc) * SW + wb + g];
            af[1] = Kt[(k0 + cc) * SW + wb + g + 8];
            af[2] = Kt[(k0 + 4 + cc) * SW + wb + g];
            af[3] = Kt[(k0 + 4 + cc) * SW + wb + g + 8];
            #pragma unroll
            for (int vp = 0; vp < 5; vp++) {
                uint32_t vv[4];
                ldsm4(vv, sVt, vp * 16, k0, SW, lane);
                uint32_t b0[2] = {vv[0], vv[2]}, b1[2] = {vv[1], vv[3]};
                mma_tf32(sa[2 * vp], af, b0);
                if (vp < 4) mma_tf32(sa[2 * vp + 1], af, b1);
            }
        }
        float* Sg = g_S + (long)(fb + c) * (65 * MM);
        #pragma unroll
        for (int vi = 0; vi < 9; vi++) {
            int v0 = vi * 8 + 2 * cc;
            if (v0 < 65) {
                Sg[v0 * MM + wb + g]     = sa[vi][0];
                Sg[v0 * MM + wb + g + 8] = sa[vi][2];
            }
            if (v0 + 1 < 65) {
                Sg[(v0 + 1) * MM + wb + g]     = sa[vi][1];
                Sg[(v0 + 1) * MM + wb + g + 8] = sa[vi][3];
            }
        }
    }
    __threadfence();
    __syncthreads();
    if (tid == 0) atomicAdd(&g_flag[fb + c], 1);

    // ---- A = Q·K^T over m, causal mask, C-frag -> A-frag (regs) ----
    uint32_t aA[16][4];
    {
        float acc[16][4];
        #pragma unroll
        for (int ti = 0; ti < 16; ti++)
            #pragma unroll
            for (int r = 0; r < 4; r++) acc[ti][r] = 0.f;
        #pragma unroll 2
        for (int k0 = 0; k0 < MM; k0 += 8) {
            uint32_t af[4];
            ldsm4(af, sQt, wb, k0, SW, lane);
            #pragma unroll
            for (int tp = 0; tp < 8; tp++) {
                uint32_t kk[4];
                ldsm4(kk, sKt, tp * 16, k0, SW, lane);
                uint32_t b0[2] = {kk[0], kk[2]}, b1[2] = {kk[1], kk[3]};
                mma_tf32(acc[2 * tp],     af, b0);
                mma_tf32(acc[2 * tp + 1], af, b1);
            }
        }
        int srcA = (g << 2) | (cc >> 1);
        int srcB = srcA + 2;
        bool odd = cc & 1;
        int nlo = wb + g, nhi = wb + g + 8;
        #pragma unroll
        for (int ti = 0; ti < 16; ti++) {
            int t0 = ti * 8 + 2 * cc;
            float m0 = (t0     <= nlo) ? acc[ti][0] : 0.f;
            float m1 = (t0 + 1 <= nlo) ? acc[ti][1] : 0.f;
            float m2 = (t0     <= nhi) ? acc[ti][2] : 0.f;
            float m3 = (t0 + 1 <= nhi) ? acc[ti][3] : 0.f;
            float x0 = __shfl_sync(0xffffffffu, m0, srcA);
            float x1 = __shfl_sync(0xffffffffu, m1, srcA);
            float x2 = __shfl_sync(0xffffffffu, m2, srcA);
            float x3 = __shfl_sync(0xffffffffu, m3, srcA);
            float y0 = __shfl_sync(0xffffffffu, m0, srcB);
            float y1 = __shfl_sync(0xffffffffu, m1, srcB);
            float y2 = __shfl_sync(0xffffffffu, m2, srcB);
            float y3 = __shfl_sync(0xffffffffu, m3, srcB);
            aA[ti][0] = f2tf32(odd ? x1 : x0);
            aA[ti][1] = f2tf32(odd ? x3 : x2);
            aA[ti][2] = f2tf32(odd ? y1 : y0);
            aA[ti][3] = f2tf32(odd ? y3 : y2);
        }
    }

    // ---- wait for prior chunks; accumulate prefix in regs ----
    float run[33];
    #pragma unroll
    for (int i = 0; i < 33; i++) run[i] = 0.f;
    if (tid == 0) {
        for (int pc = 0; pc < c; pc++)
            while (ld_acquire(&g_flag[fb + pc]) < s1) __nanosleep(64);
        __threadfence();
    }
    __syncthreads();
    for (int pc = 0; pc < c; pc++) {
        const float* Sg = g_S + (long)(fb + pc) * (65 * MM);
        #pragma unroll
        for (int i = 0; i < 33; i++) {
            int e = tid + 256 * i;
            if (e < 65 * MM) run[i] += Sg[e];
        }
    }
    __syncthreads();   // all warps done with Kt (A-phase reads) before overlay

    // ---- Ssl[v][m] tf32 over Kt region; zero pad rows 65..79 ----
    #pragma unroll
    for (int i = 0; i < 33; i++) {
        int e = tid + 256 * i;
        if (e < 65 * MM) Ssl[(e >> 7) * SW + (e & 127)] = f2tf32(run[i]);
    }
    for (int idx = tid; idx < 15 * MM; idx += 256) {
        int v = 65 + idx / MM, m = idx & 127;
        Ssl[v * SW + m] = 0u;
    }
    __syncthreads();

    // ---- phase b: O[n][72v] = A@Vaug + Q@Ssl; col 64 = normalizer ----
    float accB[9][4];
    #pragma unroll
    for (int vi = 0; vi < 9; vi++)
        #pragma unroll
        for (int r = 0; r < 4; r++) accB[vi][r] = 0.f;
    #pragma unroll 2
    for (int kb = 0; kb < 16; kb++) {            // intra: k = t
        #pragma unroll
        for (int vp = 0; vp < 5; vp++) {
            uint32_t vv[4];
            ldsm4(vv, sVt, vp * 16, kb * 8, SW, lane);
            uint32_t b0[2] = {vv[0], vv[2]}, b1[2] = {vv[1], vv[3]};
            mma_tf32(accB[2 * vp], aA[kb], b0);
            if (vp < 4) mma_tf32(accB[2 * vp + 1], aA[kb], b1);
        }
    }
    #pragma unroll 2
    for (int k0 = 0; k0 < MM; k0 += 8) {         // inter: k = m
        uint32_t qa[4];
        ldsm4(qa, sQt, wb, k0, SW, lane);
        #pragma unroll
        for (int vp = 0; vp < 5; vp++) {
            uint32_t ss[4];
            ldsm4(ss, sKt, vp * 16, k0, SW, lane);
            uint32_t b0[2] = {ss[0], ss[2]}, b1[2] = {ss[1], ss[3]};
            mma_tf32(accB[2 * vp], qa, b0);
            if (vp < 4) mma_tf32(accB[2 * vp + 1], qa, b1);
        }
    }

    // ---- epilogue: divide by norm, stage Os[v][n], coalesced store ----
    {
        float nlo = __shfl_sync(0xffffffffu, accB[8][0], lane & ~3);
        float nhi = __shfl_sync(0xffffffffu, accB[8][2], lane & ~3);
        float rlo = 1.f / nlo, rhi = 1.f / nhi;
        __syncthreads();   // Vt reads done -> Os overlays region B
        #pragma unroll
        for (int vi = 0; vi < 8; vi++) {
            int v = vi * 8 + 2 * cc;
            Os[v * SW + wb + g]           = __float_as_uint(accB[vi][0] * rlo);
            Os[(v + 1) * SW + wb + g]     = __float_as_uint(accB[vi][1] * rlo);
            Os[v * SW + wb + g + 8]       = __float_as_uint(accB[vi][2] * rhi);
            Os[(v + 1) * SW + wb + g + 8] = __float_as_uint(accB[vi][3] * rhi);
        }
        __syncthreads();
        for (int idx = tid; idx < DVV * CHUNK; idx += 256) {
            int v = idx >> 7, n = idx & 127;
            outp[(h * DVV + v) * NSEQ + n0 + n] = __uint_as_float(Os[v * SW + n]);
        }
    }
}

static const int SM_BYTES = SM_U32 * 4;   // 206848

extern "C" void kernel_launch(void* const* d_in, const int* in_sizes, int n_in,
                              void* d_out, int out_size) {
    const float* keys     = (const float*)d_in[0];
    const float* values   = (const float*)d_in[1];
    const float* queries  = (const float*)d_in[2];
    const float* features = (const float*)d_in[3];
    float* outp = (float*)d_out;

    cudaFuncSetAttribute(favor_kernel, cudaFuncAttributeMaxDynamicSharedMemorySize, SM_BYTES);
    favor_kernel<<<dim3(NCHUNK, HH), 256, SM_BYTES>>>(keys, values, queries, features, outp);
}